// round 2
// baseline (speedup 1.0000x reference)
#include <cuda_runtime.h>
#include <math.h>

#define NTHREADS 256
#define BT 16
#define HD 512

struct Smem {
    float hA[BT * HD];
    float hB[BT * HD];
    float in[BT * 16];
    float x[BT][12];
    float fn[BT][3];
    float part[96];
    float Im[9];
    float Iinv[9];
};

__device__ __forceinline__ float leaky(float v) { return v >= 0.f ? v : 0.01f * v; }

// 512 -> 512 layer: out = leaky(in @ W + b). Block tile BT=16 rows x 512 cols.
// Thread tile: 4 rows x 8 cols (ty in [0,4), tx in [0,64)).
__device__ __forceinline__ void layer512(const float* __restrict__ si,
                                         float* __restrict__ so,
                                         const float* __restrict__ W,
                                         const float* __restrict__ bv,
                                         int ty, int tx) {
    const int row0 = ty * 4;
    const int col = tx * 8;
    float acc[4][8];
#pragma unroll
    for (int r = 0; r < 4; r++)
#pragma unroll
        for (int c = 0; c < 8; c++) acc[r][c] = 0.f;

    const float* wp = W + col;
    const float* ap = si + row0 * HD;
#pragma unroll 4
    for (int k = 0; k < HD; k++) {
        float4 wa = *reinterpret_cast<const float4*>(wp);
        float4 wb = *reinterpret_cast<const float4*>(wp + 4);
        wp += HD;
        float w[8] = {wa.x, wa.y, wa.z, wa.w, wb.x, wb.y, wb.z, wb.w};
        float a[4];
#pragma unroll
        for (int r = 0; r < 4; r++) a[r] = ap[r * HD + k];
#pragma unroll
        for (int r = 0; r < 4; r++)
#pragma unroll
            for (int c = 0; c < 8; c++) acc[r][c] = fmaf(a[r], w[c], acc[r][c]);
    }
    float4 ba = *reinterpret_cast<const float4*>(bv + col);
    float4 bb = *reinterpret_cast<const float4*>(bv + col + 4);
    float bs[8] = {ba.x, ba.y, ba.z, ba.w, bb.x, bb.y, bb.z, bb.w};
#pragma unroll
    for (int r = 0; r < 4; r++) {
        float4 o1, o2;
        o1.x = leaky(acc[r][0] + bs[0]);
        o1.y = leaky(acc[r][1] + bs[1]);
        o1.z = leaky(acc[r][2] + bs[2]);
        o1.w = leaky(acc[r][3] + bs[3]);
        o2.x = leaky(acc[r][4] + bs[4]);
        o2.y = leaky(acc[r][5] + bs[5]);
        o2.z = leaky(acc[r][6] + bs[6]);
        o2.w = leaky(acc[r][7] + bs[7]);
        float* op = so + (row0 + r) * HD + col;
        *reinterpret_cast<float4*>(op) = o1;
        *reinterpret_cast<float4*>(op + 4) = o2;
    }
}

// 16 -> 512 layer
__device__ __forceinline__ void layer16(const float* __restrict__ si,
                                        float* __restrict__ so,
                                        const float* __restrict__ W,
                                        const float* __restrict__ bv,
                                        int ty, int tx) {
    const int row0 = ty * 4;
    const int col = tx * 8;
    float acc[4][8];
#pragma unroll
    for (int r = 0; r < 4; r++)
#pragma unroll
        for (int c = 0; c < 8; c++) acc[r][c] = 0.f;

    const float* wp = W + col;
#pragma unroll
    for (int k = 0; k < 16; k++) {
        float4 wa = *reinterpret_cast<const float4*>(wp);
        float4 wb = *reinterpret_cast<const float4*>(wp + 4);
        wp += HD;
        float w[8] = {wa.x, wa.y, wa.z, wa.w, wb.x, wb.y, wb.z, wb.w};
        float a[4];
#pragma unroll
        for (int r = 0; r < 4; r++) a[r] = si[(row0 + r) * 16 + k];
#pragma unroll
        for (int r = 0; r < 4; r++)
#pragma unroll
            for (int c = 0; c < 8; c++) acc[r][c] = fmaf(a[r], w[c], acc[r][c]);
    }
    float4 ba = *reinterpret_cast<const float4*>(bv + col);
    float4 bb = *reinterpret_cast<const float4*>(bv + col + 4);
    float bs[8] = {ba.x, ba.y, ba.z, ba.w, bb.x, bb.y, bb.z, bb.w};
#pragma unroll
    for (int r = 0; r < 4; r++) {
        float4 o1, o2;
        o1.x = leaky(acc[r][0] + bs[0]);
        o1.y = leaky(acc[r][1] + bs[1]);
        o1.z = leaky(acc[r][2] + bs[2]);
        o1.w = leaky(acc[r][3] + bs[3]);
        o2.x = leaky(acc[r][4] + bs[4]);
        o2.y = leaky(acc[r][5] + bs[5]);
        o2.z = leaky(acc[r][6] + bs[6]);
        o2.w = leaky(acc[r][7] + bs[7]);
        float* op = so + (row0 + r) * HD + col;
        *reinterpret_cast<float4*>(op) = o1;
        *reinterpret_cast<float4*>(op + 4) = o2;
    }
}

// Rigid-body derivatives, M (moments) == 0.
__device__ __forceinline__ void derivs(const float x[12], float F0, float F1, float F2,
                                       const float Im[9], const float Iv[9], float dx[12]) {
    float V0 = x[3], V1 = x[4], V2 = x[5];
    float phi = x[6], th = x[7], ps = x[8];
    float w0 = x[9], w1 = x[10], w2 = x[11];
    float cph = cosf(phi), sph = sinf(phi);
    float cth = cosf(th), sth = sinf(th);
    float cps = cosf(ps), sps = sinf(ps);

    dx[0] = (cth * cps) * V0 + (sph * sth * cps - cph * sps) * V1 + (cph * sth * cps + sph * sps) * V2;
    dx[1] = (cth * sps) * V0 + (sph * sth * sps + cph * cps) * V1 + (cph * sth * sps - sph * cps) * V2;
    dx[2] = (-sth) * V0 + (sph * cth) * V1 + (cph * cth) * V2;

    dx[3] = F0 / 1.5f - (w1 * V2 - w2 * V1);
    dx[4] = F1 / 1.5f - (w2 * V0 - w0 * V2);
    dx[5] = F2 / 1.5f - (w0 * V1 - w1 * V0);

    float tth = tanf(th);
    float cthc = fmaxf(cth, 1e-6f);
    float ic = 1.0f / cthc;
    dx[6] = w0 + sph * tth * w1 + cph * tth * w2;
    dx[7] = cph * w1 - sph * w2;
    dx[8] = (sph * ic) * w1 + (cph * ic) * w2;

    float Iw0 = Im[0] * w0 + Im[1] * w1 + Im[2] * w2;
    float Iw1 = Im[3] * w0 + Im[4] * w1 + Im[5] * w2;
    float Iw2 = Im[6] * w0 + Im[7] * w1 + Im[8] * w2;
    float c0 = w1 * Iw2 - w2 * Iw1;
    float c1 = w2 * Iw0 - w0 * Iw2;
    float c2 = w0 * Iw1 - w1 * Iw0;
    dx[9]  = -(Iv[0] * c0 + Iv[1] * c1 + Iv[2] * c2);
    dx[10] = -(Iv[3] * c0 + Iv[4] * c1 + Iv[5] * c2);
    dx[11] = -(Iv[6] * c0 + Iv[7] * c1 + Iv[8] * c2);
}

extern "C" __global__ void __launch_bounds__(NTHREADS, 1)
wm_rollout(const float* __restrict__ x_t, const float* __restrict__ act,
           const float* __restrict__ Imat_g,
           const float* __restrict__ W0, const float* __restrict__ b0,
           const float* __restrict__ W1, const float* __restrict__ b1,
           const float* __restrict__ W2, const float* __restrict__ b2,
           const float* __restrict__ W3, const float* __restrict__ b3,
           const int* __restrict__ seqp, float* __restrict__ out, int Bn) {
    extern __shared__ char smc[];
    Smem& S = *reinterpret_cast<Smem*>(smc);
    const int tid = threadIdx.x;
    const int ty = tid >> 6;
    const int tx = tid & 63;

    const int T = seqp[0];
    const int steps = T - 1;
    float* outF = out;                                   // [B, 6, T-1]
    float* outX = out + (size_t)Bn * 6 * steps;          // [B, 12, T]

    if (tid == 0) {
        float a = Imat_g[0], b = Imat_g[1], c = Imat_g[2];
        float d = Imat_g[3], e = Imat_g[4], f = Imat_g[5];
        float g = Imat_g[6], h = Imat_g[7], i = Imat_g[8];
        float A = e * i - f * h;
        float Bc = -(d * i - f * g);
        float C = d * h - e * g;
        float det = a * A + b * Bc + c * C;
        float id = 1.0f / det;
        S.Iinv[0] = A * id;            S.Iinv[1] = (c * h - b * i) * id;  S.Iinv[2] = (b * f - c * e) * id;
        S.Iinv[3] = Bc * id;           S.Iinv[4] = (a * i - c * g) * id;  S.Iinv[5] = (c * d - a * f) * id;
        S.Iinv[6] = C * id;            S.Iinv[7] = (b * g - a * h) * id;  S.Iinv[8] = (a * e - b * d) * id;
#pragma unroll
        for (int k = 0; k < 9; k++) S.Im[k] = Imat_g[k];
    }

    if (tid < BT) {
        const int row = tid;
        const size_t bidx = (size_t)blockIdx.x * BT + row;
#pragma unroll
        for (int s = 0; s < 12; s++) {
            float v = x_t[bidx * 12 + s];
            S.x[row][s] = v;
            outX[bidx * 12 * T + (size_t)s * T + 0] = v;
        }
    }
    __syncthreads();

    // per-thread copies of I and I^-1 for RK4 threads
    float ImR[9], IvR[9];
    if (tid < BT) {
#pragma unroll
        for (int k = 0; k < 9; k++) { ImR[k] = S.Im[k]; IvR[k] = S.Iinv[k]; }
    }

    for (int t = 0; t < steps; t++) {
        // ---- build MLP input [norm_x(12), norm_act(4)] ----
        if (tid < BT) {
            const int row = tid;
            const size_t bidx = (size_t)blockIdx.x * BT + row;
            float* ip = &S.in[row * 16];
            ip[0] = S.x[row][0] * 1.2732395447351628f;
            ip[1] = S.x[row][1] * 0.5f;
            ip[2] = S.x[row][2] * 1.2732395447351628f;
            ip[3] = S.x[row][3] * 0.1f;
            ip[4] = S.x[row][4] * 0.016666666666666666f;
            ip[5] = S.x[row][5] * 0.016666666666666666f;
#pragma unroll
            for (int s = 6; s < 12; s++) ip[s] = 0.f;
#pragma unroll
            for (int a = 0; a < 4; a++)
                ip[12 + a] = (act[(bidx * 4 + a) * T + (t + 1)] - 1500.0f) / 500.0f;
        }
        __syncthreads();

        layer16(S.in, S.hA, W0, b0, ty, tx);
        __syncthreads();
        layer512(S.hA, S.hB, W1, b1, ty, tx);
        __syncthreads();
        layer512(S.hB, S.hA, W2, b2, ty, tx);
        __syncthreads();

        // ---- layer 3: only output cols 0..2 are used (moments are zero) ----
        if (tid < 96) {
            const int o = tid >> 1;          // 0..47
            const int half = tid & 1;
            const int row = o / 3;
            const int cc = o - row * 3;
            const float* hp = S.hA + row * HD + half * 256;
            const float* wp = W3 + (half * 256) * 6 + cc;
            float s = 0.f;
#pragma unroll 8
            for (int k = 0; k < 256; k++) s = fmaf(hp[k], wp[k * 6], s);
            S.part[tid] = s;
        }
        __syncthreads();
        if (tid < 48) {
            const int row = tid / 3;
            const int cc = tid - row * 3;
            S.fn[row][cc] = S.part[2 * tid] + S.part[2 * tid + 1] + b3[cc];
        }
        __syncthreads();

        // ---- forces + RK4 + outputs ----
        if (tid < BT) {
            const int row = tid;
            const size_t bidx = (size_t)blockIdx.x * BT + row;
            const float F0 = S.fn[row][0] - 0.5f;
            const float F1 = S.fn[row][1] * (-0.4f) - 10.0f;
            const float F2 = S.fn[row][2] * 0.2f - 0.1f;

            float* fo = outF + bidx * 6 * steps + t;
            fo[0 * steps] = F0;
            fo[1 * steps] = F1;
            fo[2 * steps] = F2;
            fo[3 * steps] = 0.f;
            fo[4 * steps] = 0.f;
            fo[5 * steps] = 0.f;

            float xx[12];
#pragma unroll
            for (int s = 0; s < 12; s++) xx[s] = S.x[row][s];
            float k1[12], k2[12], k3[12], k4[12], tm[12];
            derivs(xx, F0, F1, F2, ImR, IvR, k1);
#pragma unroll
            for (int s = 0; s < 12; s++) tm[s] = xx[s] + 0.005f * k1[s];
            derivs(tm, F0, F1, F2, ImR, IvR, k2);
#pragma unroll
            for (int s = 0; s < 12; s++) tm[s] = xx[s] + 0.005f * k2[s];
            derivs(tm, F0, F1, F2, ImR, IvR, k3);
#pragma unroll
            for (int s = 0; s < 12; s++) tm[s] = xx[s] + 0.01f * k3[s];
            derivs(tm, F0, F1, F2, ImR, IvR, k4);
            const float w6 = (float)(0.01 / 6.0);
#pragma unroll
            for (int s = 0; s < 12; s++)
                xx[s] = xx[s] + w6 * (k1[s] + 2.f * k2[s] + 2.f * k3[s] + k4[s]);

            float* xo = outX + bidx * 12 * T + (t + 1);
#pragma unroll
            for (int s = 0; s < 12; s++) {
                S.x[row][s] = xx[s];
                xo[(size_t)s * T] = xx[s];
            }
        }
        __syncthreads();
    }
}

extern "C" void kernel_launch(void* const* d_in, const int* in_sizes, int n_in,
                              void* d_out, int out_size) {
    // metadata order follows setup_inputs() dict insertion order:
    // 0: x_t, 1: act_inps, 2: I_mat, 3: seq_len, 4..11: W0,b0,W1,b1,W2,b2,W3,b3
    const float* x_t = (const float*)d_in[0];
    const float* act = (const float*)d_in[1];
    const float* Im  = (const float*)d_in[2];
    const int* seqp  = (const int*)d_in[3];
    const float* W0  = (const float*)d_in[4];
    const float* b0  = (const float*)d_in[5];
    const float* W1  = (const float*)d_in[6];
    const float* b1  = (const float*)d_in[7];
    const float* W2  = (const float*)d_in[8];
    const float* b2  = (const float*)d_in[9];
    const float* W3  = (const float*)d_in[10];
    const float* b3  = (const float*)d_in[11];

    const int Bn = in_sizes[0] / 12;
    const int grid = Bn / BT;
    const size_t sm = sizeof(Smem);

    cudaFuncSetAttribute(wm_rollout, cudaFuncAttributeMaxDynamicSharedMemorySize, (int)sm);
    wm_rollout<<<grid, NTHREADS, sm>>>(x_t, act, Im, W0, b0, W1, b1, W2, b2, W3, b3,
                                       seqp, (float*)d_out, Bn);
}

// round 3
// speedup vs baseline: 1.1341x; 1.1341x over previous
#include <cuda_runtime.h>
#include <math.h>

#define NTHREADS 256
#define BT 16
#define HD 512

typedef unsigned long long ull;

struct Smem {
    float hA[BT * HD];
    float hB[BT * HD];
    float in[BT * 16];
    float x[BT][12];
    float fn[BT][3];
    float part[96];
    float Im[9];
    float Iinv[9];
};

__device__ __forceinline__ float leaky(float v) { return v >= 0.f ? v : 0.01f * v; }

// packed f32x2 fma (sm_100+): d = a*b + c, two fp32 lanes per instruction
__device__ __forceinline__ ull fma2(ull a, ull b, ull c) {
    ull d;
    asm("fma.rn.f32x2 %0, %1, %2, %3;" : "=l"(d) : "l"(a), "l"(b), "l"(c));
    return d;
}
__device__ __forceinline__ ull pack2(float x) {
    ull r;
    asm("mov.b64 %0, {%1, %1};" : "=l"(r) : "f"(x));
    return r;
}
__device__ __forceinline__ float2 unpack2(ull v) {
    float2 f;
    asm("mov.b64 {%0, %1}, %2;" : "=f"(f.x), "=f"(f.y) : "l"(v));
    return f;
}

// 512 -> 512 layer: out = leaky(in @ W + b).
// Block tile BT=16 rows x 512 cols; thread tile 4 rows x 8 cols.
// Thread (ty in [0,4), tx in [0,64)) owns rows ty*4..+3, cols {tx*4..+3, tx*4+256..+259}.
// Lanes are 16B apart on W -> fully-coalesced LDG.128 (4 lines, 100% utilization).
__device__ __forceinline__ void layer512(const float* __restrict__ si,
                                         float* __restrict__ so,
                                         const float* __restrict__ W,
                                         const float* __restrict__ bv,
                                         int ty, int tx) {
    const int row0 = ty * 4;
    const int c0 = tx * 4;
    ull acc[4][4];
#pragma unroll
    for (int r = 0; r < 4; r++)
#pragma unroll
        for (int j = 0; j < 4; j++) acc[r][j] = 0ULL;

    const float* ap = si + row0 * HD;
    const float* wp = W + c0;
#pragma unroll 4
    for (int k = 0; k < HD; k++) {
        ulonglong2 wA = *reinterpret_cast<const ulonglong2*>(wp);
        ulonglong2 wB = *reinterpret_cast<const ulonglong2*>(wp + 256);
        wp += HD;
        ull w[4] = {wA.x, wA.y, wB.x, wB.y};
        ull a2[4];
#pragma unroll
        for (int r = 0; r < 4; r++) a2[r] = pack2(ap[r * HD + k]);
#pragma unroll
        for (int r = 0; r < 4; r++)
#pragma unroll
            for (int j = 0; j < 4; j++) acc[r][j] = fma2(a2[r], w[j], acc[r][j]);
    }
    float4 bA = *reinterpret_cast<const float4*>(bv + c0);
    float4 bB = *reinterpret_cast<const float4*>(bv + c0 + 256);
    float bs[8] = {bA.x, bA.y, bA.z, bA.w, bB.x, bB.y, bB.z, bB.w};
#pragma unroll
    for (int r = 0; r < 4; r++) {
        float2 p0 = unpack2(acc[r][0]);
        float2 p1 = unpack2(acc[r][1]);
        float2 p2 = unpack2(acc[r][2]);
        float2 p3 = unpack2(acc[r][3]);
        float4 oA, oB;
        oA.x = leaky(p0.x + bs[0]);
        oA.y = leaky(p0.y + bs[1]);
        oA.z = leaky(p1.x + bs[2]);
        oA.w = leaky(p1.y + bs[3]);
        oB.x = leaky(p2.x + bs[4]);
        oB.y = leaky(p2.y + bs[5]);
        oB.z = leaky(p3.x + bs[6]);
        oB.w = leaky(p3.y + bs[7]);
        float* op = so + (row0 + r) * HD;
        *reinterpret_cast<float4*>(op + c0) = oA;
        *reinterpret_cast<float4*>(op + c0 + 256) = oB;
    }
}

// 16 -> 512 layer (same mapping, K=16)
__device__ __forceinline__ void layer16(const float* __restrict__ si,
                                        float* __restrict__ so,
                                        const float* __restrict__ W,
                                        const float* __restrict__ bv,
                                        int ty, int tx) {
    const int row0 = ty * 4;
    const int c0 = tx * 4;
    ull acc[4][4];
#pragma unroll
    for (int r = 0; r < 4; r++)
#pragma unroll
        for (int j = 0; j < 4; j++) acc[r][j] = 0ULL;

    const float* wp = W + c0;
#pragma unroll
    for (int k = 0; k < 16; k++) {
        ulonglong2 wA = *reinterpret_cast<const ulonglong2*>(wp);
        ulonglong2 wB = *reinterpret_cast<const ulonglong2*>(wp + 256);
        wp += HD;
        ull w[4] = {wA.x, wA.y, wB.x, wB.y};
        ull a2[4];
#pragma unroll
        for (int r = 0; r < 4; r++) a2[r] = pack2(si[(row0 + r) * 16 + k]);
#pragma unroll
        for (int r = 0; r < 4; r++)
#pragma unroll
            for (int j = 0; j < 4; j++) acc[r][j] = fma2(a2[r], w[j], acc[r][j]);
    }
    float4 bA = *reinterpret_cast<const float4*>(bv + c0);
    float4 bB = *reinterpret_cast<const float4*>(bv + c0 + 256);
    float bs[8] = {bA.x, bA.y, bA.z, bA.w, bB.x, bB.y, bB.z, bB.w};
#pragma unroll
    for (int r = 0; r < 4; r++) {
        float2 p0 = unpack2(acc[r][0]);
        float2 p1 = unpack2(acc[r][1]);
        float2 p2 = unpack2(acc[r][2]);
        float2 p3 = unpack2(acc[r][3]);
        float4 oA, oB;
        oA.x = leaky(p0.x + bs[0]);
        oA.y = leaky(p0.y + bs[1]);
        oA.z = leaky(p1.x + bs[2]);
        oA.w = leaky(p1.y + bs[3]);
        oB.x = leaky(p2.x + bs[4]);
        oB.y = leaky(p2.y + bs[5]);
        oB.z = leaky(p3.x + bs[6]);
        oB.w = leaky(p3.y + bs[7]);
        float* op = so + (row0 + r) * HD;
        *reinterpret_cast<float4*>(op + c0) = oA;
        *reinterpret_cast<float4*>(op + c0 + 256) = oB;
    }
}

// Rigid-body derivatives, M (moments) == 0.
__device__ __forceinline__ void derivs(const float x[12], float F0, float F1, float F2,
                                       const float Im[9], const float Iv[9], float dx[12]) {
    float V0 = x[3], V1 = x[4], V2 = x[5];
    float phi = x[6], th = x[7], ps = x[8];
    float w0 = x[9], w1 = x[10], w2 = x[11];
    float cph = cosf(phi), sph = sinf(phi);
    float cth = cosf(th), sth = sinf(th);
    float cps = cosf(ps), sps = sinf(ps);

    dx[0] = (cth * cps) * V0 + (sph * sth * cps - cph * sps) * V1 + (cph * sth * cps + sph * sps) * V2;
    dx[1] = (cth * sps) * V0 + (sph * sth * sps + cph * cps) * V1 + (cph * sth * sps - sph * cps) * V2;
    dx[2] = (-sth) * V0 + (sph * cth) * V1 + (cph * cth) * V2;

    dx[3] = F0 / 1.5f - (w1 * V2 - w2 * V1);
    dx[4] = F1 / 1.5f - (w2 * V0 - w0 * V2);
    dx[5] = F2 / 1.5f - (w0 * V1 - w1 * V0);

    float tth = tanf(th);
    float cthc = fmaxf(cth, 1e-6f);
    float ic = 1.0f / cthc;
    dx[6] = w0 + sph * tth * w1 + cph * tth * w2;
    dx[7] = cph * w1 - sph * w2;
    dx[8] = (sph * ic) * w1 + (cph * ic) * w2;

    float Iw0 = Im[0] * w0 + Im[1] * w1 + Im[2] * w2;
    float Iw1 = Im[3] * w0 + Im[4] * w1 + Im[5] * w2;
    float Iw2 = Im[6] * w0 + Im[7] * w1 + Im[8] * w2;
    float c0 = w1 * Iw2 - w2 * Iw1;
    float c1 = w2 * Iw0 - w0 * Iw2;
    float c2 = w0 * Iw1 - w1 * Iw0;
    dx[9]  = -(Iv[0] * c0 + Iv[1] * c1 + Iv[2] * c2);
    dx[10] = -(Iv[3] * c0 + Iv[4] * c1 + Iv[5] * c2);
    dx[11] = -(Iv[6] * c0 + Iv[7] * c1 + Iv[8] * c2);
}

extern "C" __global__ void __launch_bounds__(NTHREADS, 1)
wm_rollout(const float* __restrict__ x_t, const float* __restrict__ act,
           const float* __restrict__ Imat_g,
           const float* __restrict__ W0, const float* __restrict__ b0,
           const float* __restrict__ W1, const float* __restrict__ b1,
           const float* __restrict__ W2, const float* __restrict__ b2,
           const float* __restrict__ W3, const float* __restrict__ b3,
           const int* __restrict__ seqp, float* __restrict__ out, int Bn) {
    extern __shared__ char smc[];
    Smem& S = *reinterpret_cast<Smem*>(smc);
    const int tid = threadIdx.x;
    const int ty = tid >> 6;
    const int tx = tid & 63;

    const int T = seqp[0];
    const int steps = T - 1;
    float* outF = out;                                   // [B, 6, T-1]
    float* outX = out + (size_t)Bn * 6 * steps;          // [B, 12, T]

    if (tid == 0) {
        float a = Imat_g[0], b = Imat_g[1], c = Imat_g[2];
        float d = Imat_g[3], e = Imat_g[4], f = Imat_g[5];
        float g = Imat_g[6], h = Imat_g[7], i = Imat_g[8];
        float A = e * i - f * h;
        float Bc = -(d * i - f * g);
        float C = d * h - e * g;
        float det = a * A + b * Bc + c * C;
        float id = 1.0f / det;
        S.Iinv[0] = A * id;            S.Iinv[1] = (c * h - b * i) * id;  S.Iinv[2] = (b * f - c * e) * id;
        S.Iinv[3] = Bc * id;           S.Iinv[4] = (a * i - c * g) * id;  S.Iinv[5] = (c * d - a * f) * id;
        S.Iinv[6] = C * id;            S.Iinv[7] = (b * g - a * h) * id;  S.Iinv[8] = (a * e - b * d) * id;
#pragma unroll
        for (int k = 0; k < 9; k++) S.Im[k] = Imat_g[k];
    }

    if (tid < BT) {
        const int row = tid;
        const size_t bidx = (size_t)blockIdx.x * BT + row;
#pragma unroll
        for (int s = 0; s < 12; s++) {
            float v = x_t[bidx * 12 + s];
            S.x[row][s] = v;
            outX[bidx * 12 * T + (size_t)s * T + 0] = v;
        }
    }
    __syncthreads();

    // per-thread copies of I and I^-1 for RK4 threads
    float ImR[9], IvR[9];
    if (tid < BT) {
#pragma unroll
        for (int k = 0; k < 9; k++) { ImR[k] = S.Im[k]; IvR[k] = S.Iinv[k]; }
    }

    for (int t = 0; t < steps; t++) {
        // ---- build MLP input [norm_x(12), norm_act(4)] ----
        if (tid < BT) {
            const int row = tid;
            const size_t bidx = (size_t)blockIdx.x * BT + row;
            float* ip = &S.in[row * 16];
            ip[0] = S.x[row][0] * 1.2732395447351628f;
            ip[1] = S.x[row][1] * 0.5f;
            ip[2] = S.x[row][2] * 1.2732395447351628f;
            ip[3] = S.x[row][3] * 0.1f;
            ip[4] = S.x[row][4] * 0.016666666666666666f;
            ip[5] = S.x[row][5] * 0.016666666666666666f;
#pragma unroll
            for (int s = 6; s < 12; s++) ip[s] = 0.f;
#pragma unroll
            for (int a = 0; a < 4; a++)
                ip[12 + a] = (act[(bidx * 4 + a) * T + (t + 1)] - 1500.0f) / 500.0f;
        }
        __syncthreads();

        layer16(S.in, S.hA, W0, b0, ty, tx);
        __syncthreads();
        layer512(S.hA, S.hB, W1, b1, ty, tx);
        __syncthreads();
        layer512(S.hB, S.hA, W2, b2, ty, tx);
        __syncthreads();

        // ---- layer 3: only output cols 0..2 are used (moments are zero) ----
        if (tid < 96) {
            const int o = tid >> 1;          // 0..47
            const int half = tid & 1;
            const int row = o / 3;
            const int cc = o - row * 3;
            const float* hp = S.hA + row * HD + half * 256;
            const float* wp = W3 + (half * 256) * 6 + cc;
            float s = 0.f;
#pragma unroll 8
            for (int k = 0; k < 256; k++) s = fmaf(hp[k], wp[k * 6], s);
            S.part[tid] = s;
        }
        __syncthreads();
        if (tid < 48) {
            const int row = tid / 3;
            const int cc = tid - row * 3;
            S.fn[row][cc] = S.part[2 * tid] + S.part[2 * tid + 1] + b3[cc];
        }
        __syncthreads();

        // ---- forces + RK4 + outputs ----
        if (tid < BT) {
            const int row = tid;
            const size_t bidx = (size_t)blockIdx.x * BT + row;
            const float F0 = S.fn[row][0] - 0.5f;
            const float F1 = S.fn[row][1] * (-0.4f) - 10.0f;
            const float F2 = S.fn[row][2] * 0.2f - 0.1f;

            float* fo = outF + bidx * 6 * steps + t;
            fo[0 * steps] = F0;
            fo[1 * steps] = F1;
            fo[2 * steps] = F2;
            fo[3 * steps] = 0.f;
            fo[4 * steps] = 0.f;
            fo[5 * steps] = 0.f;

            float xx[12];
#pragma unroll
            for (int s = 0; s < 12; s++) xx[s] = S.x[row][s];
            float k1[12], k2[12], k3[12], k4[12], tm[12];
            derivs(xx, F0, F1, F2, ImR, IvR, k1);
#pragma unroll
            for (int s = 0; s < 12; s++) tm[s] = xx[s] + 0.005f * k1[s];
            derivs(tm, F0, F1, F2, ImR, IvR, k2);
#pragma unroll
            for (int s = 0; s < 12; s++) tm[s] = xx[s] + 0.005f * k2[s];
            derivs(tm, F0, F1, F2, ImR, IvR, k3);
#pragma unroll
            for (int s = 0; s < 12; s++) tm[s] = xx[s] + 0.01f * k3[s];
            derivs(tm, F0, F1, F2, ImR, IvR, k4);
            const float w6 = (float)(0.01 / 6.0);
#pragma unroll
            for (int s = 0; s < 12; s++)
                xx[s] = xx[s] + w6 * (k1[s] + 2.f * k2[s] + 2.f * k3[s] + k4[s]);

            float* xo = outX + bidx * 12 * T + (t + 1);
#pragma unroll
            for (int s = 0; s < 12; s++) {
                S.x[row][s] = xx[s];
                xo[(size_t)s * T] = xx[s];
            }
        }
        __syncthreads();
    }
}

extern "C" void kernel_launch(void* const* d_in, const int* in_sizes, int n_in,
                              void* d_out, int out_size) {
    // metadata order follows setup_inputs() dict insertion order:
    // 0: x_t, 1: act_inps, 2: I_mat, 3: seq_len, 4..11: W0,b0,W1,b1,W2,b2,W3,b3
    const float* x_t = (const float*)d_in[0];
    const float* act = (const float*)d_in[1];
    const float* Im  = (const float*)d_in[2];
    const int* seqp  = (const int*)d_in[3];
    const float* W0  = (const float*)d_in[4];
    const float* b0  = (const float*)d_in[5];
    const float* W1  = (const float*)d_in[6];
    const float* b1  = (const float*)d_in[7];
    const float* W2  = (const float*)d_in[8];
    const float* b2  = (const float*)d_in[9];
    const float* W3  = (const float*)d_in[10];
    const float* b3  = (const float*)d_in[11];

    const int Bn = in_sizes[0] / 12;
    const int grid = Bn / BT;
    const size_t sm = sizeof(Smem);

    cudaFuncSetAttribute(wm_rollout, cudaFuncAttributeMaxDynamicSharedMemorySize, (int)sm);
    wm_rollout<<<grid, NTHREADS, sm>>>(x_t, act, Im, W0, b0, W1, b1, W2, b2, W3, b3,
                                       seqp, (float*)d_out, Bn);
}

// round 4
// speedup vs baseline: 1.2950x; 1.1418x over previous
#include <cuda_runtime.h>
#include <math.h>

#define NTHREADS 512
#define BT 16
#define HD 512
#define ST 20   // column stride (floats) for column-major activations; 80B keeps 16B alignment

typedef unsigned long long ull;

struct Smem {
    float hA[HD * ST];   // column-major: hA[k*ST + row], rows 0..15 used
    float hB[HD * ST];
    float in[16 * ST];   // column-major MLP input
    float x[BT][12];
    float fn[BT][3];
    float part[96];
    float Im[9];
    float Iinv[9];
};

__device__ __forceinline__ float leaky(float v) { return v >= 0.f ? v : 0.01f * v; }

// packed f32x2 fma (sm_100+): two fp32 lanes per instruction
__device__ __forceinline__ ull fma2(ull a, ull b, ull c) {
    ull d;
    asm("fma.rn.f32x2 %0, %1, %2, %3;" : "=l"(d) : "l"(a), "l"(b), "l"(c));
    return d;
}
__device__ __forceinline__ ull pack2(float x) {
    ull r;
    asm("mov.b64 %0, {%1, %1};" : "=l"(r) : "f"(x));
    return r;
}
__device__ __forceinline__ float2 unpack2(ull v) {
    float2 f;
    asm("mov.b64 {%0, %1}, %2;" : "=f"(f.x), "=f"(f.y) : "l"(v));
    return f;
}

// Generic K -> 512 layer with column-major activations.
// si: column-major input  [K][rows]   (si[k*ST + row])
// so: column-major output [512][rows] (so[c*ST + row])
// Thread (ty in {0,1}, tx in [0,256)): rows ty*8..+7, cols {tx, tx+256}.
// Per k: a = 2x LDS.128 (4 row-pairs, already packed), w = 2 coalesced scalar LDG + pack2.
template <int K>
__device__ __forceinline__ void layer_col(const float* __restrict__ si,
                                          float* __restrict__ so,
                                          const float* __restrict__ W,
                                          const float* __restrict__ bv,
                                          int ty, int tx) {
    const int r0 = ty * 8;
    ull acc[4][2];
#pragma unroll
    for (int p = 0; p < 4; p++) { acc[p][0] = 0ULL; acc[p][1] = 0ULL; }

    const float* wp = W + tx;
    const float* ap = si + r0;
#pragma unroll 4
    for (int k = 0; k < K; k++) {
        ull w0 = pack2(wp[0]);
        ull w1 = pack2(wp[256]);
        wp += HD;
        ulonglong2 aA = *reinterpret_cast<const ulonglong2*>(ap);
        ulonglong2 aB = *reinterpret_cast<const ulonglong2*>(ap + 4);
        ap += ST;
        acc[0][0] = fma2(aA.x, w0, acc[0][0]);
        acc[0][1] = fma2(aA.x, w1, acc[0][1]);
        acc[1][0] = fma2(aA.y, w0, acc[1][0]);
        acc[1][1] = fma2(aA.y, w1, acc[1][1]);
        acc[2][0] = fma2(aB.x, w0, acc[2][0]);
        acc[2][1] = fma2(aB.x, w1, acc[2][1]);
        acc[3][0] = fma2(aB.y, w0, acc[3][0]);
        acc[3][1] = fma2(aB.y, w1, acc[3][1]);
    }

    const float b0 = bv[tx];
    const float b1 = bv[tx + 256];
    float4 oA0, oA1, oB0, oB1;
    {
        float2 v0 = unpack2(acc[0][0]);
        float2 v1 = unpack2(acc[1][0]);
        float2 v2 = unpack2(acc[2][0]);
        float2 v3 = unpack2(acc[3][0]);
        oA0.x = leaky(v0.x + b0); oA0.y = leaky(v0.y + b0);
        oA0.z = leaky(v1.x + b0); oA0.w = leaky(v1.y + b0);
        oA1.x = leaky(v2.x + b0); oA1.y = leaky(v2.y + b0);
        oA1.z = leaky(v3.x + b0); oA1.w = leaky(v3.y + b0);
    }
    {
        float2 v0 = unpack2(acc[0][1]);
        float2 v1 = unpack2(acc[1][1]);
        float2 v2 = unpack2(acc[2][1]);
        float2 v3 = unpack2(acc[3][1]);
        oB0.x = leaky(v0.x + b1); oB0.y = leaky(v0.y + b1);
        oB0.z = leaky(v1.x + b1); oB0.w = leaky(v1.y + b1);
        oB1.x = leaky(v2.x + b1); oB1.y = leaky(v2.y + b1);
        oB1.z = leaky(v3.x + b1); oB1.w = leaky(v3.y + b1);
    }
    float* o0 = so + tx * ST + r0;
    float* o1 = so + (tx + 256) * ST + r0;
    *reinterpret_cast<float4*>(o0) = oA0;
    *reinterpret_cast<float4*>(o0 + 4) = oA1;
    *reinterpret_cast<float4*>(o1) = oB0;
    *reinterpret_cast<float4*>(o1 + 4) = oB1;
}

// Rigid-body derivatives, M (moments) == 0.
__device__ __forceinline__ void derivs(const float x[12], float F0, float F1, float F2,
                                       const float Im[9], const float Iv[9], float dx[12]) {
    float V0 = x[3], V1 = x[4], V2 = x[5];
    float phi = x[6], th = x[7], ps = x[8];
    float w0 = x[9], w1 = x[10], w2 = x[11];
    float cph = cosf(phi), sph = sinf(phi);
    float cth = cosf(th), sth = sinf(th);
    float cps = cosf(ps), sps = sinf(ps);

    dx[0] = (cth * cps) * V0 + (sph * sth * cps - cph * sps) * V1 + (cph * sth * cps + sph * sps) * V2;
    dx[1] = (cth * sps) * V0 + (sph * sth * sps + cph * cps) * V1 + (cph * sth * sps - sph * cps) * V2;
    dx[2] = (-sth) * V0 + (sph * cth) * V1 + (cph * cth) * V2;

    dx[3] = F0 / 1.5f - (w1 * V2 - w2 * V1);
    dx[4] = F1 / 1.5f - (w2 * V0 - w0 * V2);
    dx[5] = F2 / 1.5f - (w0 * V1 - w1 * V0);

    float tth = tanf(th);
    float cthc = fmaxf(cth, 1e-6f);
    float ic = 1.0f / cthc;
    dx[6] = w0 + sph * tth * w1 + cph * tth * w2;
    dx[7] = cph * w1 - sph * w2;
    dx[8] = (sph * ic) * w1 + (cph * ic) * w2;

    float Iw0 = Im[0] * w0 + Im[1] * w1 + Im[2] * w2;
    float Iw1 = Im[3] * w0 + Im[4] * w1 + Im[5] * w2;
    float Iw2 = Im[6] * w0 + Im[7] * w1 + Im[8] * w2;
    float c0 = w1 * Iw2 - w2 * Iw1;
    float c1 = w2 * Iw0 - w0 * Iw2;
    float c2 = w0 * Iw1 - w1 * Iw0;
    dx[9]  = -(Iv[0] * c0 + Iv[1] * c1 + Iv[2] * c2);
    dx[10] = -(Iv[3] * c0 + Iv[4] * c1 + Iv[5] * c2);
    dx[11] = -(Iv[6] * c0 + Iv[7] * c1 + Iv[8] * c2);
}

extern "C" __global__ void __launch_bounds__(NTHREADS, 1)
wm_rollout(const float* __restrict__ x_t, const float* __restrict__ act,
           const float* __restrict__ Imat_g,
           const float* __restrict__ W0, const float* __restrict__ b0,
           const float* __restrict__ W1, const float* __restrict__ b1,
           const float* __restrict__ W2, const float* __restrict__ b2,
           const float* __restrict__ W3, const float* __restrict__ b3,
           const int* __restrict__ seqp, float* __restrict__ out, int Bn) {
    extern __shared__ char smc[];
    Smem& S = *reinterpret_cast<Smem*>(smc);
    const int tid = threadIdx.x;
    const int ty = tid >> 8;       // 0..1
    const int tx = tid & 255;      // 0..255

    const int T = seqp[0];
    const int steps = T - 1;
    float* outF = out;                                   // [B, 6, T-1]
    float* outX = out + (size_t)Bn * 6 * steps;          // [B, 12, T]

    if (tid == 0) {
        float a = Imat_g[0], b = Imat_g[1], c = Imat_g[2];
        float d = Imat_g[3], e = Imat_g[4], f = Imat_g[5];
        float g = Imat_g[6], h = Imat_g[7], i = Imat_g[8];
        float A = e * i - f * h;
        float Bc = -(d * i - f * g);
        float C = d * h - e * g;
        float det = a * A + b * Bc + c * C;
        float id = 1.0f / det;
        S.Iinv[0] = A * id;            S.Iinv[1] = (c * h - b * i) * id;  S.Iinv[2] = (b * f - c * e) * id;
        S.Iinv[3] = Bc * id;           S.Iinv[4] = (a * i - c * g) * id;  S.Iinv[5] = (c * d - a * f) * id;
        S.Iinv[6] = C * id;            S.Iinv[7] = (b * g - a * h) * id;  S.Iinv[8] = (a * e - b * d) * id;
#pragma unroll
        for (int k = 0; k < 9; k++) S.Im[k] = Imat_g[k];
    }

    if (tid < BT) {
        const int row = tid;
        const size_t bidx = (size_t)blockIdx.x * BT + row;
#pragma unroll
        for (int s = 0; s < 12; s++) {
            float v = x_t[bidx * 12 + s];
            S.x[row][s] = v;
            outX[bidx * 12 * T + (size_t)s * T + 0] = v;
        }
    }
    __syncthreads();

    // per-thread copies of I and I^-1 for RK4 threads
    float ImR[9], IvR[9];
    if (tid < BT) {
#pragma unroll
        for (int k = 0; k < 9; k++) { ImR[k] = S.Im[k]; IvR[k] = S.Iinv[k]; }
    }

    for (int t = 0; t < steps; t++) {
        // ---- build MLP input, column-major: in[k*ST + row] ----
        if (tid < BT) {
            const int row = tid;
            const size_t bidx = (size_t)blockIdx.x * BT + row;
            S.in[0 * ST + row] = S.x[row][0] * 1.2732395447351628f;
            S.in[1 * ST + row] = S.x[row][1] * 0.5f;
            S.in[2 * ST + row] = S.x[row][2] * 1.2732395447351628f;
            S.in[3 * ST + row] = S.x[row][3] * 0.1f;
            S.in[4 * ST + row] = S.x[row][4] * 0.016666666666666666f;
            S.in[5 * ST + row] = S.x[row][5] * 0.016666666666666666f;
#pragma unroll
            for (int s = 6; s < 12; s++) S.in[s * ST + row] = 0.f;
#pragma unroll
            for (int a = 0; a < 4; a++)
                S.in[(12 + a) * ST + row] = (act[(bidx * 4 + a) * T + (t + 1)] - 1500.0f) / 500.0f;
        }
        __syncthreads();

        layer_col<16>(S.in, S.hA, W0, b0, ty, tx);
        __syncthreads();
        layer_col<HD>(S.hA, S.hB, W1, b1, ty, tx);
        __syncthreads();
        layer_col<HD>(S.hB, S.hA, W2, b2, ty, tx);
        __syncthreads();

        // ---- layer 3: only output cols 0..2 used (moments are zero) ----
        // hA is column-major: hA[k*ST + row]
        if (tid < 96) {
            const int o = tid >> 1;          // 0..47
            const int half = tid & 1;
            const int row = o / 3;
            const int cc = o - row * 3;
            const float* hp = S.hA + (half * 256) * ST + row;
            const float* wp = W3 + (half * 256) * 6 + cc;
            float s = 0.f;
#pragma unroll 8
            for (int k = 0; k < 256; k++) s = fmaf(hp[k * ST], wp[k * 6], s);
            S.part[tid] = s;
        }
        __syncthreads();
        if (tid < 48) {
            const int row = tid / 3;
            const int cc = tid - row * 3;
            S.fn[row][cc] = S.part[2 * tid] + S.part[2 * tid + 1] + b3[cc];
        }
        __syncthreads();

        // ---- forces + RK4 + outputs ----
        if (tid < BT) {
            const int row = tid;
            const size_t bidx = (size_t)blockIdx.x * BT + row;
            const float F0 = S.fn[row][0] - 0.5f;
            const float F1 = S.fn[row][1] * (-0.4f) - 10.0f;
            const float F2 = S.fn[row][2] * 0.2f - 0.1f;

            float* fo = outF + bidx * 6 * steps + t;
            fo[0 * steps] = F0;
            fo[1 * steps] = F1;
            fo[2 * steps] = F2;
            fo[3 * steps] = 0.f;
            fo[4 * steps] = 0.f;
            fo[5 * steps] = 0.f;

            float xx[12];
#pragma unroll
            for (int s = 0; s < 12; s++) xx[s] = S.x[row][s];
            float k1[12], k2[12], k3[12], k4[12], tm[12];
            derivs(xx, F0, F1, F2, ImR, IvR, k1);
#pragma unroll
            for (int s = 0; s < 12; s++) tm[s] = xx[s] + 0.005f * k1[s];
            derivs(tm, F0, F1, F2, ImR, IvR, k2);
#pragma unroll
            for (int s = 0; s < 12; s++) tm[s] = xx[s] + 0.005f * k2[s];
            derivs(tm, F0, F1, F2, ImR, IvR, k3);
#pragma unroll
            for (int s = 0; s < 12; s++) tm[s] = xx[s] + 0.01f * k3[s];
            derivs(tm, F0, F1, F2, ImR, IvR, k4);
            const float w6 = (float)(0.01 / 6.0);
#pragma unroll
            for (int s = 0; s < 12; s++)
                xx[s] = xx[s] + w6 * (k1[s] + 2.f * k2[s] + 2.f * k3[s] + k4[s]);

            float* xo = outX + bidx * 12 * T + (t + 1);
#pragma unroll
            for (int s = 0; s < 12; s++) {
                S.x[row][s] = xx[s];
                xo[(size_t)s * T] = xx[s];
            }
        }
        __syncthreads();
    }
}

extern "C" void kernel_launch(void* const* d_in, const int* in_sizes, int n_in,
                              void* d_out, int out_size) {
    // metadata order follows setup_inputs() dict insertion order:
    // 0: x_t, 1: act_inps, 2: I_mat, 3: seq_len, 4..11: W0,b0,W1,b1,W2,b2,W3,b3
    const float* x_t = (const float*)d_in[0];
    const float* act = (const float*)d_in[1];
    const float* Im  = (const float*)d_in[2];
    const int* seqp  = (const int*)d_in[3];
    const float* W0  = (const float*)d_in[4];
    const float* b0  = (const float*)d_in[5];
    const float* W1  = (const float*)d_in[6];
    const float* b1  = (const float*)d_in[7];
    const float* W2  = (const float*)d_in[8];
    const float* b2  = (const float*)d_in[9];
    const float* W3  = (const float*)d_in[10];
    const float* b3  = (const float*)d_in[11];

    const int Bn = in_sizes[0] / 12;
    const int grid = Bn / BT;
    const size_t sm = sizeof(Smem);

    cudaFuncSetAttribute(wm_rollout, cudaFuncAttributeMaxDynamicSharedMemorySize, (int)sm);
    wm_rollout<<<grid, NTHREADS, sm>>>(x_t, act, Im, W0, b0, W1, b1, W2, b2, W3, b3,
                                       seqp, (float*)d_out, Bn);
}